// round 8
// baseline (speedup 1.0000x reference)
#include <cuda_runtime.h>
#include <cuda_bf16.h>
#include <cstdint>
#include <stdint.h>
#include <math.h>

#define N_NODES 8192
#define K_NB    32
#define D_DIM   128
#define H_DIM   256
#define NPB     2          // nodes per block -> M = 64 rows

typedef unsigned int       u32;
typedef unsigned long long u64;

__device__ float g_P[N_NODES * H_DIM];   // x @ W1[:128] + b1
__device__ float g_Q[N_NODES * H_DIM];   // x @ W1[128:]
// W2^T bf16 hi/lo as 8 N-tile smem images (32 rows x 256 k, swizzled)
__device__ __align__(16) unsigned char g_W2img[8][2][16384];

// ---------------- helpers ----------------
__device__ __forceinline__ u32 smem_u32(const void* p) {
    return (u32)__cvta_generic_to_shared(p);
}
__device__ __forceinline__ void cp_async16(u32 saddr, const void* gaddr) {
    asm volatile("cp.async.cg.shared.global [%0], [%1], 16;" :: "r"(saddr), "l"(gaddr));
}
__device__ __forceinline__ void cp_commit() { asm volatile("cp.async.commit_group;"); }
template <int N>
__device__ __forceinline__ void cp_wait() {
    asm volatile("cp.async.wait_group %0;" :: "n"(N) : "memory");
}
__device__ __forceinline__ void ldsm4(u32* r, u32 addr) {
    asm volatile("ldmatrix.sync.aligned.m8n8.x4.shared.b16 {%0,%1,%2,%3}, [%4];"
                 : "=r"(r[0]), "=r"(r[1]), "=r"(r[2]), "=r"(r[3]) : "r"(addr));
}
__device__ __forceinline__ void mma_bf16(float* c, const u32* a, const u32* b) {
    asm volatile(
        "mma.sync.aligned.m16n8k16.row.col.f32.bf16.bf16.f32 "
        "{%0,%1,%2,%3}, {%4,%5,%6,%7}, {%8,%9}, {%0,%1,%2,%3};"
        : "+f"(c[0]), "+f"(c[1]), "+f"(c[2]), "+f"(c[3])
        : "r"(a[0]), "r"(a[1]), "r"(a[2]), "r"(a[3]), "r"(b[0]), "r"(b[1]));
}
__device__ __forceinline__ u32 bf2pack(float lo_e, float hi_e) {
    __nv_bfloat162 t = __floats2bfloat162_rn(lo_e, hi_e);  // .x = lo_e (low half)
    return *(u32*)&t;
}

// ---------------------------------------------------------------------------
__global__ void zero_kernel(float4* __restrict__ out, int n4) {
    int stride = gridDim.x * blockDim.x;
    float4 z = make_float4(0.f, 0.f, 0.f, 0.f);
    for (int i = blockIdx.x * blockDim.x + threadIdx.x; i < n4; i += stride)
        out[i] = z;
}

// ---------------------------------------------------------------------------
#define ROWS_PER_BLK 16
__global__ __launch_bounds__(256) void pq_kernel(
    const float* __restrict__ x, const float* __restrict__ W1,
    const float* __restrict__ b1)
{
    __shared__ float xs[ROWS_PER_BLK * D_DIM];
    const int t = threadIdx.x;
    const int row0 = blockIdx.x * ROWS_PER_BLK;

    const float4* xsrc = (const float4*)(x + (size_t)row0 * D_DIM);
    float4* xdst = (float4*)xs;
    #pragma unroll
    for (int i = 0; i < (ROWS_PER_BLK * D_DIM / 4) / 256; i++)
        xdst[t + i * 256] = xsrc[t + i * 256];
    __syncthreads();

    float accP[ROWS_PER_BLK], accQ[ROWS_PER_BLK];
    #pragma unroll
    for (int r = 0; r < ROWS_PER_BLK; r++) { accP[r] = 0.f; accQ[r] = 0.f; }

    #pragma unroll 4
    for (int d = 0; d < D_DIM; d++) {
        float wp = W1[d * H_DIM + t];
        float wq = W1[(D_DIM + d) * H_DIM + t];
        #pragma unroll
        for (int r = 0; r < ROWS_PER_BLK; r++) {
            float xv = xs[r * D_DIM + d];
            accP[r] = fmaf(xv, wp, accP[r]);
            accQ[r] = fmaf(xv, wq, accQ[r]);
        }
    }
    float bb = b1[t];
    #pragma unroll
    for (int r = 0; r < ROWS_PER_BLK; r++) {
        g_P[(size_t)(row0 + r) * H_DIM + t] = accP[r] + bb;
        g_Q[(size_t)(row0 + r) * H_DIM + t] = accQ[r];
    }
}

// ---------------------------------------------------------------------------
// W2 -> 8 N-tile images of W2^T (bf16 hi/lo): image[tile][term], row nn
// (0..31, 512B = 256 k), 16B chunks XOR-swizzled by (nn&7)<<4.
// ---------------------------------------------------------------------------
__global__ void w2prep_kernel(const float* __restrict__ W2) {
    const int k = blockIdx.x;      // 0..255
    const int n = threadIdx.x;     // 0..255
    float v = W2[k * H_DIM + n];
    __nv_bfloat16 h = __float2bfloat16(v);
    __nv_bfloat16 l = __float2bfloat16(v - __bfloat162float(h));
    int tile = n >> 5, nn = n & 31;
    u32 off = (u32)(nn * 512 + k * 2) ^ (u32)((nn & 7) << 4);
    *(__nv_bfloat16*)&g_W2img[tile][0][off] = h;
    *(__nv_bfloat16*)&g_W2img[tile][1][off] = l;
}

// ---------------------------------------------------------------------------
// Main kernel: 4096 blocks x 256 threads, 2 nodes -> M=64, 2 CTAs/SM.
// smem: h1 hi (32KB) + h1 lo (32KB) + W2 tile single buffer (32KB) = 96KB.
// Warps 0-3 own 16 M-rows each for cols [0,16) of each tile; warps 4-7 the
// same rows for cols [16,32). cc[8] accumulators, per-tile epilogue fold.
// ---------------------------------------------------------------------------
#define NT        8
#define TILE_B    32768      // one tile image: hi 16KB + lo 16KB
#define SMEM_DYN  (65536 + TILE_B)

__global__ __launch_bounds__(256, 2) void mlp_kernel(
    const int* __restrict__ nbrs,
    const float* __restrict__ t_arr, const float* __restrict__ e_hat,
    const float* __restrict__ b2, const float* __restrict__ W3,
    const float* __restrict__ b3, const float* __restrict__ b_scal,
    float* __restrict__ ypred, float* __restrict__ pairwise)
{
    extern __shared__ __align__(128) unsigned char dsm[];
    unsigned char* h1hi_p = dsm;             // 32KB
    unsigned char* h1lo_p = dsm + 32768;     // 32KB
    unsigned char* w2s_p  = dsm + 65536;     // 32KB single buffer
    __shared__ float red_s[2][64];
    __shared__ int   cjs_s[64];
    __shared__ float b2s[H_DIM], w3s[H_DIM];

    const int tid  = threadIdx.x;
    const int lane = tid & 31;
    const int warp = tid >> 5;

    b2s[tid] = b2[tid];
    w3s[tid] = W3[tid];
    if (tid < 64)
        cjs_s[tid] = nbrs[(blockIdx.x * NPB + (tid >> 5)) * (K_NB + 1) + 1 + (tid & 31)];

    const u32 w2sa = smem_u32(w2s_p);
    const u32 h1hi = smem_u32(h1hi_p);
    const u32 h1lo = smem_u32(h1lo_p);

    // prefetch W2 tile 0 (32KB; 128B per thread)
    {
        const unsigned char* src = (const unsigned char*)g_W2img[0];
        #pragma unroll
        for (int t = 0; t < 8; t++) {
            int idx = (t * 256 + tid) * 16;
            cp_async16(w2sa + idx, src + idx);
        }
        cp_commit();
    }
    __syncthreads();   // cjs_s, b2s, w3s visible

    // ---- build full h1 (hi/lo bf16, swizzled): thread -> row tid/4, k-quarter tid&3
    {
        const int mrow = tid >> 2, qt = tid & 3;
        const int node_m = blockIdx.x * NPB + (mrow >> 5);
        const int cjm = cjs_s[mrow];
        const float4* Qp = (const float4*)(g_Q + (size_t)cjm    * H_DIM) + qt * 16;
        const float4* Pp = (const float4*)(g_P + (size_t)node_m * H_DIM) + qt * 16;
        const u32 h1base = (u32)(mrow * 512);
        const u32 swm    = (u32)((mrow & 7) << 4);
        #pragma unroll
        for (int g8 = 0; g8 < 8; g8++) {
            float4 q0 = Qp[g8 * 2], q1 = Qp[g8 * 2 + 1];
            float4 p0 = Pp[g8 * 2], p1 = Pp[g8 * 2 + 1];
            float v0 = fmaxf(p0.x + q0.x, 0.f), v1 = fmaxf(p0.y + q0.y, 0.f);
            float v2 = fmaxf(p0.z + q0.z, 0.f), v3 = fmaxf(p0.w + q0.w, 0.f);
            float v4 = fmaxf(p1.x + q1.x, 0.f), v5 = fmaxf(p1.y + q1.y, 0.f);
            float v6 = fmaxf(p1.z + q1.z, 0.f), v7 = fmaxf(p1.w + q1.w, 0.f);
            float h0 = __bfloat162float(__float2bfloat16(v0));
            float h1v = __bfloat162float(__float2bfloat16(v1));
            float h2 = __bfloat162float(__float2bfloat16(v2));
            float h3 = __bfloat162float(__float2bfloat16(v3));
            float h4 = __bfloat162float(__float2bfloat16(v4));
            float h5 = __bfloat162float(__float2bfloat16(v5));
            float h6 = __bfloat162float(__float2bfloat16(v6));
            float h7 = __bfloat162float(__float2bfloat16(v7));
            uint4 hi4, lo4;
            hi4.x = bf2pack(h0, h1v); hi4.y = bf2pack(h2, h3);
            hi4.z = bf2pack(h4, h5);  hi4.w = bf2pack(h6, h7);
            lo4.x = bf2pack(v0 - h0, v1 - h1v); lo4.y = bf2pack(v2 - h2, v3 - h3);
            lo4.z = bf2pack(v4 - h4, v5 - h5);  lo4.w = bf2pack(v6 - h6, v7 - h7);
            u32 off = (h1base + (u32)((qt * 8 + g8) * 16)) ^ swm;
            *(uint4*)(h1hi_p + off) = hi4;
            *(uint4*)(h1lo_p + off) = lo4;
        }
    }

    // ---- MMA geometry: warp&3 -> M rows, warp>>2 -> 16-col half of tile
    const int m_base = (warp & 3) * 16;
    const int nhalf  = warp >> 2;
    const int mA  = m_base + ((lane >> 3) & 1) * 8 + (lane & 7);
    const int kbA = (lane >> 4) * 8;
    const u32 aswz = (u32)((mA & 7) << 4);
    const int nB7  = (lane & 7) + ((lane >> 4) & 1) * 8;
    const int kkB7 = ((lane >> 3) & 1) * 8;
    const u32 bswz = (u32)(((nB7 & 7) << 4));
    const int tig  = lane & 3;

    float cc[8];
    #pragma unroll
    for (int i = 0; i < 8; i++) cc[i] = 0.f;
    float acc0 = 0.f, acc1 = 0.f;

    cp_wait<0>();
    __syncthreads();   // h1 + tile 0 visible

    #pragma unroll 1
    for (int tile = 0; tile < NT; tile++) {
        #pragma unroll 4
        for (int kt = 0; kt < 16; kt++) {
            u32 offA = ((u32)(mA * 512 + (kt * 16 + kbA) * 2)) ^ aswz;
            u32 ah[4], al[4];
            ldsm4(ah, h1hi + offA);
            ldsm4(al, h1lo + offA);
            u32 offB = ((u32)((nhalf * 16 + nB7) * 512 + (kt * 16 + kkB7) * 2)) ^ bswz;
            u32 bh[4], bl[4];
            ldsm4(bh, w2sa + offB);
            ldsm4(bl, w2sa + 16384 + offB);
            mma_bf16(cc,     ah, bh);
            mma_bf16(cc + 4, ah, bh + 2);
            mma_bf16(cc,     al, bh);
            mma_bf16(cc + 4, al, bh + 2);
            mma_bf16(cc,     ah, bl);
            mma_bf16(cc + 4, ah, bl + 2);
        }
        __syncthreads();   // all warps done reading tile buffer

        if (tile + 1 < NT) {
            const unsigned char* src = (const unsigned char*)g_W2img[tile + 1];
            #pragma unroll
            for (int t = 0; t < 8; t++) {
                int idx = (t * 256 + tid) * 16;
                cp_async16(w2sa + idx, src + idx);
            }
            cp_commit();
        }

        // fold tile into per-row layer-3 accumulators (no smem dependency)
        #pragma unroll
        for (int g = 0; g < 2; g++) {
            int col = tile * 32 + nhalf * 16 + g * 8 + 2 * tig;
            float b0 = b2s[col], b1v = b2s[col + 1];
            float w0 = w3s[col], w1v = w3s[col + 1];
            acc0 = fmaf(fmaxf(cc[g * 4 + 0] + b0, 0.f), w0, acc0);
            acc0 = fmaf(fmaxf(cc[g * 4 + 1] + b1v, 0.f), w1v, acc0);
            acc1 = fmaf(fmaxf(cc[g * 4 + 2] + b0, 0.f), w0, acc1);
            acc1 = fmaf(fmaxf(cc[g * 4 + 3] + b1v, 0.f), w1v, acc1);
            cc[g * 4 + 0] = 0.f; cc[g * 4 + 1] = 0.f;
            cc[g * 4 + 2] = 0.f; cc[g * 4 + 3] = 0.f;
        }

        if (tile + 1 < NT) { cp_wait<0>(); }
        __syncthreads();   // next tile visible / safe
    }

    // quad-reduce (4 lanes share a row-pair), then combine N-halves via smem
    acc0 += __shfl_xor_sync(0xffffffffu, acc0, 1);
    acc0 += __shfl_xor_sync(0xffffffffu, acc0, 2);
    acc1 += __shfl_xor_sync(0xffffffffu, acc1, 1);
    acc1 += __shfl_xor_sync(0xffffffffu, acc1, 2);
    if (tig == 0) {
        red_s[nhalf][m_base + (lane >> 2)]     = acc0;
        red_s[nhalf][m_base + 8 + (lane >> 2)] = acc1;
    }
    __syncthreads();

    // ---- softmax + outputs: warp w (0-1) handles node w
    if (warp < NPB) {
        const int j = lane;
        const int node = blockIdx.x * NPB + warp;
        float mlp = red_s[0][warp * 32 + j] + red_s[1][warp * 32 + j] + b3[0];
        int cj = cjs_s[warp * 32 + j];

        float a = b_scal[0] * fabsf(mlp);
        float amax = a;
        #pragma unroll
        for (int o = 16; o > 0; o >>= 1)
            amax = fmaxf(amax, __shfl_xor_sync(0xffffffffu, amax, o));
        float e = __expf(a - amax);
        float esum = e;
        #pragma unroll
        for (int o = 16; o > 0; o >>= 1)
            esum += __shfl_xor_sync(0xffffffffu, esum, o);
        float wgt = mlp * (e / esum);

        float prop = t_arr[cj] - e_hat[cj];
        float yp = prop * wgt;
        #pragma unroll
        for (int o = 16; o > 0; o >>= 1)
            yp += __shfl_xor_sync(0xffffffffu, yp, o);
        if (lane == 0) ypred[node] = yp;

        // serial scatter (ascending j, last write wins)
        float* prow = pairwise + (size_t)node * N_NODES;
        #pragma unroll
        for (int jj = 0; jj < K_NB; jj++) {
            float wj = __shfl_sync(0xffffffffu, wgt, jj);
            int  cjj = __shfl_sync(0xffffffffu, cj,  jj);
            if (lane == 0) prow[cjj] = wj;
        }
        if (lane == 0) prow[node] = 0.f;
    }
}

// ---------------------------------------------------------------------------
extern "C" void kernel_launch(void* const* d_in, const int* in_sizes, int n_in,
                              void* d_out, int out_size) {
    const float* x     = (const float*)d_in[0];
    const int*   nbrs  = (const int*)  d_in[1];
    const float* t_arr = (const float*)d_in[2];
    const float* e_hat = (const float*)d_in[3];
    const float* W1    = (const float*)d_in[4];
    const float* b1    = (const float*)d_in[5];
    const float* W2    = (const float*)d_in[6];
    const float* b2    = (const float*)d_in[7];
    const float* W3    = (const float*)d_in[8];
    const float* b3    = (const float*)d_in[9];
    const float* bsc   = (const float*)d_in[10];

    float* ypred    = (float*)d_out;
    float* pairwise = ypred + N_NODES;

    static int smem_set = 0;
    if (!smem_set) {
        cudaFuncSetAttribute(mlp_kernel,
                             cudaFuncAttributeMaxDynamicSharedMemorySize,
                             SMEM_DYN);
        smem_set = 1;
    }

    int n4 = out_size / 4;
    zero_kernel<<<8192, 256>>>((float4*)d_out, n4);
    pq_kernel<<<N_NODES / ROWS_PER_BLK, 256>>>(x, W1, b1);
    w2prep_kernel<<<H_DIM, 256>>>(W2);
    mlp_kernel<<<N_NODES / NPB, 256, SMEM_DYN>>>(nbrs, t_arr, e_hat, b2, W3,
                                                 b3, bsc, ypred, pairwise);
}

// round 9
// speedup vs baseline: 1.2275x; 1.2275x over previous
#include <cuda_runtime.h>
#include <cuda_fp16.h>
#include <cstdint>
#include <stdint.h>
#include <math.h>

#define N_NODES 8192
#define K_NB    32
#define D_DIM   128
#define H_DIM   256
#define NPB     2          // nodes per block -> M = 64 rows

typedef unsigned int       u32;
typedef unsigned long long u64;

__device__ float g_P[N_NODES * H_DIM];   // x @ W1[:128] + b1
__device__ float g_Q[N_NODES * H_DIM];   // x @ W1[128:]
// W2^T single-fp16 swizzled smem image: row n (512B = 256 k), 128KB
__device__ __align__(16) unsigned char g_W2h[131072];

// ---------------- helpers ----------------
__device__ __forceinline__ u32 smem_u32(const void* p) {
    return (u32)__cvta_generic_to_shared(p);
}
__device__ __forceinline__ void cp_async16(u32 saddr, const void* gaddr) {
    asm volatile("cp.async.cg.shared.global [%0], [%1], 16;" :: "r"(saddr), "l"(gaddr));
}
__device__ __forceinline__ void cp_commit() { asm volatile("cp.async.commit_group;"); }
__device__ __forceinline__ void cp_wait0() {
    asm volatile("cp.async.wait_group 0;" ::: "memory");
}
__device__ __forceinline__ void ldsm4(u32* r, u32 addr) {
    asm volatile("ldmatrix.sync.aligned.m8n8.x4.shared.b16 {%0,%1,%2,%3}, [%4];"
                 : "=r"(r[0]), "=r"(r[1]), "=r"(r[2]), "=r"(r[3]) : "r"(addr));
}
__device__ __forceinline__ void mma_f16(float* c, const u32* a, const u32* b) {
    asm volatile(
        "mma.sync.aligned.m16n8k16.row.col.f32.f16.f16.f32 "
        "{%0,%1,%2,%3}, {%4,%5,%6,%7}, {%8,%9}, {%0,%1,%2,%3};"
        : "+f"(c[0]), "+f"(c[1]), "+f"(c[2]), "+f"(c[3])
        : "r"(a[0]), "r"(a[1]), "r"(a[2]), "r"(a[3]), "r"(b[0]), "r"(b[1]));
}

// ---------------------------------------------------------------------------
__global__ void zero_kernel(float4* __restrict__ out, int n4) {
    int stride = gridDim.x * blockDim.x;
    float4 z = make_float4(0.f, 0.f, 0.f, 0.f);
    for (int i = blockIdx.x * blockDim.x + threadIdx.x; i < n4; i += stride)
        out[i] = z;
}

// ---------------------------------------------------------------------------
#define ROWS_PER_BLK 16
__global__ __launch_bounds__(256) void pq_kernel(
    const float* __restrict__ x, const float* __restrict__ W1,
    const float* __restrict__ b1)
{
    __shared__ float xs[ROWS_PER_BLK * D_DIM];
    const int t = threadIdx.x;
    const int row0 = blockIdx.x * ROWS_PER_BLK;

    const float4* xsrc = (const float4*)(x + (size_t)row0 * D_DIM);
    float4* xdst = (float4*)xs;
    #pragma unroll
    for (int i = 0; i < (ROWS_PER_BLK * D_DIM / 4) / 256; i++)
        xdst[t + i * 256] = xsrc[t + i * 256];
    __syncthreads();

    float accP[ROWS_PER_BLK], accQ[ROWS_PER_BLK];
    #pragma unroll
    for (int r = 0; r < ROWS_PER_BLK; r++) { accP[r] = 0.f; accQ[r] = 0.f; }

    #pragma unroll 4
    for (int d = 0; d < D_DIM; d++) {
        float wp = W1[d * H_DIM + t];
        float wq = W1[(D_DIM + d) * H_DIM + t];
        #pragma unroll
        for (int r = 0; r < ROWS_PER_BLK; r++) {
            float xv = xs[r * D_DIM + d];
            accP[r] = fmaf(xv, wp, accP[r]);
            accQ[r] = fmaf(xv, wq, accQ[r]);
        }
    }
    float bb = b1[t];
    #pragma unroll
    for (int r = 0; r < ROWS_PER_BLK; r++) {
        g_P[(size_t)(row0 + r) * H_DIM + t] = accP[r] + bb;
        g_Q[(size_t)(row0 + r) * H_DIM + t] = accQ[r];
    }
}

// ---------------------------------------------------------------------------
// W2 -> fp16 image of W2^T: row n (0..255, 512B = 256 k fp16), 16B chunks
// XOR-swizzled by (n&7)<<4.
// ---------------------------------------------------------------------------
__global__ void w2prep_kernel(const float* __restrict__ W2) {
    const int k = blockIdx.x;      // 0..255
    const int n = threadIdx.x;     // 0..255
    float v = W2[k * H_DIM + n];
    __half h = __float2half(v);
    u32 off = (u32)(n * 512 + k * 2) ^ (u32)((n & 7) << 4);
    *(__half*)&g_W2h[off] = h;
}

// ---------------------------------------------------------------------------
// Main kernel: 4096 blocks x 256 threads, 2 nodes -> M=64.
// smem: W2 fp16 full (128KB) + h1 hi (32KB) + h1 lo (32KB) = 192KB.
// Warp tile 32x64: warp&1 -> M half, warp>>2... (warp&1 = M, warp>>1 = N
// quarter of 64 cols). K-loop has NO syncs and NO refills.
// 2-term fp16: c += a_hi*b + a_lo*b.
// ---------------------------------------------------------------------------
#define SMEM_DYN (131072 + 65536)

__global__ __launch_bounds__(256) void mlp_kernel(
    const int* __restrict__ nbrs,
    const float* __restrict__ t_arr, const float* __restrict__ e_hat,
    const float* __restrict__ b2, const float* __restrict__ W3,
    const float* __restrict__ b3, const float* __restrict__ b_scal,
    float* __restrict__ ypred, float* __restrict__ pairwise)
{
    extern __shared__ __align__(128) unsigned char dsm[];
    unsigned char* w2s_p  = dsm;             // 128KB
    unsigned char* h1hi_p = dsm + 131072;    // 32KB
    unsigned char* h1lo_p = dsm + 163840;    // 32KB
    __shared__ float red_s[4][64];
    __shared__ int   cjs_s[64];
    __shared__ float b2s[H_DIM], w3s[H_DIM];

    const int tid  = threadIdx.x;
    const int lane = tid & 31;
    const int warp = tid >> 5;

    b2s[tid] = b2[tid];
    w3s[tid] = W3[tid];
    if (tid < 64)
        cjs_s[tid] = nbrs[(blockIdx.x * NPB + (tid >> 5)) * (K_NB + 1) + 1 + (tid & 31)];

    const u32 w2sa = smem_u32(w2s_p);
    const u32 h1hi = smem_u32(h1hi_p);
    const u32 h1lo = smem_u32(h1lo_p);

    // load full W2 image (128KB; 512B per thread)
    #pragma unroll
    for (int t = 0; t < 32; t++) {
        int idx = (t * 256 + tid) * 16;
        cp_async16(w2sa + idx, g_W2h + idx);
    }
    cp_commit();
    __syncthreads();   // cjs_s, b2s, w3s visible

    // ---- build h1 (hi/lo fp16, swizzled): thread -> row tid/4, k-quarter tid&3
    {
        const int mrow = tid >> 2, qt = tid & 3;
        const int node_m = blockIdx.x * NPB + (mrow >> 5);
        const int cjm = cjs_s[mrow];
        const float4* Qp = (const float4*)(g_Q + (size_t)cjm    * H_DIM) + qt * 16;
        const float4* Pp = (const float4*)(g_P + (size_t)node_m * H_DIM) + qt * 16;
        const u32 h1base = (u32)(mrow * 512);
        const u32 swm    = (u32)((mrow & 7) << 4);
        #pragma unroll
        for (int g8 = 0; g8 < 8; g8++) {
            float4 q0 = Qp[g8 * 2], q1 = Qp[g8 * 2 + 1];
            float4 p0 = Pp[g8 * 2], p1 = Pp[g8 * 2 + 1];
            float v0 = fmaxf(p0.x + q0.x, 0.f), v1 = fmaxf(p0.y + q0.y, 0.f);
            float v2 = fmaxf(p0.z + q0.z, 0.f), v3 = fmaxf(p0.w + q0.w, 0.f);
            float v4 = fmaxf(p1.x + q1.x, 0.f), v5 = fmaxf(p1.y + q1.y, 0.f);
            float v6 = fmaxf(p1.z + q1.z, 0.f), v7 = fmaxf(p1.w + q1.w, 0.f);
            __half2 h01 = __floats2half2_rn(v0, v1);
            __half2 h23 = __floats2half2_rn(v2, v3);
            __half2 h45 = __floats2half2_rn(v4, v5);
            __half2 h67 = __floats2half2_rn(v6, v7);
            __half2 l01 = __floats2half2_rn(v0 - __half2float(h01.x),
                                            v1 - __half2float(h01.y));
            __half2 l23 = __floats2half2_rn(v2 - __half2float(h23.x),
                                            v3 - __half2float(h23.y));
            __half2 l45 = __floats2half2_rn(v4 - __half2float(h45.x),
                                            v5 - __half2float(h45.y));
            __half2 l67 = __floats2half2_rn(v6 - __half2float(h67.x),
                                            v7 - __half2float(h67.y));
            uint4 hi4, lo4;
            hi4.x = *(u32*)&h01; hi4.y = *(u32*)&h23;
            hi4.z = *(u32*)&h45; hi4.w = *(u32*)&h67;
            lo4.x = *(u32*)&l01; lo4.y = *(u32*)&l23;
            lo4.z = *(u32*)&l45; lo4.w = *(u32*)&l67;
            u32 off = (h1base + (u32)((qt * 8 + g8) * 16)) ^ swm;
            *(uint4*)(h1hi_p + off) = hi4;
            *(uint4*)(h1lo_p + off) = lo4;
        }
    }

    // ---- MMA geometry: warp&1 -> 32-row half, warp>>1 -> 64-col quarter
    const int m_base = (warp & 1) * 32;
    const int n_base = (warp >> 1) * 64;
    const int kbA = (lane >> 4) * 8;
    const int nB7  = (lane & 7) + ((lane >> 4) & 1) * 8;
    const int kkB7 = ((lane >> 3) & 1) * 8;
    const int tig  = lane & 3;

    float cc[64];
    #pragma unroll
    for (int i = 0; i < 64; i++) cc[i] = 0.f;

    cp_wait0();
    __syncthreads();   // h1 + W2 visible

    #pragma unroll 2
    for (int kt = 0; kt < 16; kt++) {
        u32 ah[2][4], al[2][4], bb[4][4];
        #pragma unroll
        for (int fm = 0; fm < 2; fm++) {
            int mA = m_base + fm * 16 + ((lane >> 3) & 1) * 8 + (lane & 7);
            u32 offA = ((u32)(mA * 512 + (kt * 16 + kbA) * 2)) ^ (u32)((mA & 7) << 4);
            ldsm4(ah[fm], h1hi + offA);
            ldsm4(al[fm], h1lo + offA);
        }
        #pragma unroll
        for (int fb = 0; fb < 4; fb++) {
            int nB = n_base + fb * 16 + nB7;
            u32 offB = ((u32)(nB * 512 + (kt * 16 + kkB7) * 2)) ^ (u32)((nB & 7) << 4);
            ldsm4(bb[fb], w2sa + offB);
        }
        #pragma unroll
        for (int fm = 0; fm < 2; fm++) {
            #pragma unroll
            for (int fb = 0; fb < 4; fb++) {
                float* c0 = cc + (fm * 8 + 2 * fb) * 4;
                float* c1 = cc + (fm * 8 + 2 * fb + 1) * 4;
                mma_f16(c0, ah[fm], bb[fb]);
                mma_f16(c1, ah[fm], bb[fb] + 2);
                mma_f16(c0, al[fm], bb[fb]);
                mma_f16(c1, al[fm], bb[fb] + 2);
            }
        }
    }

    // ---- epilogue: fold relu(C + b2) . W3 per row
    {
        float a0 = 0.f, a1 = 0.f, a2 = 0.f, a3 = 0.f;   // rows fm0:{r,r+8} fm1:{r,r+8}
        #pragma unroll
        for (int fm = 0; fm < 2; fm++) {
            #pragma unroll
            for (int fn = 0; fn < 8; fn++) {
                int col = n_base + fn * 8 + 2 * tig;
                float b0 = b2s[col], b1v = b2s[col + 1];
                float w0 = w3s[col], w1v = w3s[col + 1];
                const float* cf = cc + (fm * 8 + fn) * 4;
                float s0 = fmaf(fmaxf(cf[0] + b0, 0.f), w0,
                                fmaxf(cf[1] + b1v, 0.f) * w1v);
                float s1 = fmaf(fmaxf(cf[2] + b0, 0.f), w0,
                                fmaxf(cf[3] + b1v, 0.f) * w1v);
                if (fm == 0) { a0 += s0; a1 += s1; }
                else         { a2 += s0; a3 += s1; }
            }
        }
        a0 += __shfl_xor_sync(0xffffffffu, a0, 1);
        a0 += __shfl_xor_sync(0xffffffffu, a0, 2);
        a1 += __shfl_xor_sync(0xffffffffu, a1, 1);
        a1 += __shfl_xor_sync(0xffffffffu, a1, 2);
        a2 += __shfl_xor_sync(0xffffffffu, a2, 1);
        a2 += __shfl_xor_sync(0xffffffffu, a2, 2);
        a3 += __shfl_xor_sync(0xffffffffu, a3, 1);
        a3 += __shfl_xor_sync(0xffffffffu, a3, 2);
        if (tig == 0) {
            int rg = lane >> 2;                    // 0..7
            int nq = warp >> 1;                    // 0..3
            red_s[nq][m_base + rg]      = a0;
            red_s[nq][m_base + 8 + rg]  = a1;
            red_s[nq][m_base + 16 + rg] = a2;
            red_s[nq][m_base + 24 + rg] = a3;
        }
    }
    __syncthreads();

    // ---- softmax + outputs: warp w (0-1) handles node w
    if (warp < NPB) {
        const int j = lane;
        const int node = blockIdx.x * NPB + warp;
        float mlp = red_s[0][warp * 32 + j] + red_s[1][warp * 32 + j]
                  + red_s[2][warp * 32 + j] + red_s[3][warp * 32 + j] + b3[0];
        int cj = cjs_s[warp * 32 + j];

        float a = b_scal[0] * fabsf(mlp);
        float amax = a;
        #pragma unroll
        for (int o = 16; o > 0; o >>= 1)
            amax = fmaxf(amax, __shfl_xor_sync(0xffffffffu, amax, o));
        float e = __expf(a - amax);
        float esum = e;
        #pragma unroll
        for (int o = 16; o > 0; o >>= 1)
            esum += __shfl_xor_sync(0xffffffffu, esum, o);
        float wgt = mlp * (e / esum);

        float prop = t_arr[cj] - e_hat[cj];
        float yp = prop * wgt;
        #pragma unroll
        for (int o = 16; o > 0; o >>= 1)
            yp += __shfl_xor_sync(0xffffffffu, yp, o);
        if (lane == 0) ypred[node] = yp;

        // serial scatter (ascending j, last write wins)
        float* prow = pairwise + (size_t)node * N_NODES;
        #pragma unroll
        for (int jj = 0; jj < K_NB; jj++) {
            float wj = __shfl_sync(0xffffffffu, wgt, jj);
            int  cjj = __shfl_sync(0xffffffffu, cj,  jj);
            if (lane == 0) prow[cjj] = wj;
        }
        if (lane == 0) prow[node] = 0.f;
    }
}

// ---------------------------------------------------------------------------
extern "C" void kernel_launch(void* const* d_in, const int* in_sizes, int n_in,
                              void* d_out, int out_size) {
    const float* x     = (const float*)d_in[0];
    const int*   nbrs  = (const int*)  d_in[1];
    const float* t_arr = (const float*)d_in[2];
    const float* e_hat = (const float*)d_in[3];
    const float* W1    = (const float*)d_in[4];
    const float* b1    = (const float*)d_in[5];
    const float* W2    = (const float*)d_in[6];
    const float* b2    = (const float*)d_in[7];
    const float* W3    = (const float*)d_in[8];
    const float* b3    = (const float*)d_in[9];
    const float* bsc   = (const float*)d_in[10];

    float* ypred    = (float*)d_out;
    float* pairwise = ypred + N_NODES;

    static int smem_set = 0;
    if (!smem_set) {
        cudaFuncSetAttribute(mlp_kernel,
                             cudaFuncAttributeMaxDynamicSharedMemorySize,
                             SMEM_DYN);
        smem_set = 1;
    }

    int n4 = out_size / 4;
    zero_kernel<<<8192, 256>>>((float4*)d_out, n4);
    pq_kernel<<<N_NODES / ROWS_PER_BLK, 256>>>(x, W1, b1);
    w2prep_kernel<<<H_DIM, 256>>>(W2);
    mlp_kernel<<<N_NODES / NPB, 256, SMEM_DYN>>>(nbrs, t_arr, e_hat, b2, W3,
                                                 b3, bsc, ypred, pairwise);
}